// round 7
// baseline (speedup 1.0000x reference)
#include <cuda_runtime.h>
#include <math.h>

#define BB   32
#define TT   8192
#define SS   32
#define IND  128
#define HH   256
#define NTOK (BB*TT)
#define TPB  32                 // tokens per MLP block
#define NMLP (NTOK/TPB)         // 8192
#define NCHUNK (TT/TPB)         // 256 chunks per batch
#define NSCAN 16                // scan blocks (2 batches each)

// output section offsets (floats): emissions, state_probs, ll, trans, best_path, path_score
#define PROBS_OFF  8388608L
#define LL_OFF     16777216L
#define TRANS_OFF  16777248L
#define BP_OFF     16778272L
#define PS_OFF     17040416L

__device__ unsigned char g_bp[(size_t)NTOK * SS];
__device__ float g_trans[SS * SS];
__device__ float g_logtrans[SS * SS];
__device__ float g_loginit[SS];
__device__ int   g_last[BB];
__device__ int   g_flag[BB * NCHUNK];

__device__ __forceinline__ float gelu_exact(float v) {
    return 0.5f * v * (1.0f + erff(v * 0.70710678118654752440f));
}
__device__ __forceinline__ float wmax(float v) {
    #pragma unroll
    for (int o = 16; o; o >>= 1) v = fmaxf(v, __shfl_xor_sync(~0u, v, o));
    return v;
}
__device__ __forceinline__ float wsum(float v) {
    #pragma unroll
    for (int o = 16; o; o >>= 1) v += __shfl_xor_sync(~0u, v, o);
    return v;
}
__device__ __forceinline__ unsigned long long pk2(float lo, float hi) {
    unsigned long long r;
    asm("mov.b64 %0, {%1, %2};" : "=l"(r) : "f"(lo), "f"(hi));
    return r;
}
__device__ __forceinline__ void fma2(unsigned long long& acc, unsigned long long a,
                                     unsigned long long b) {
    asm("fma.rn.f32x2 %0, %1, %2, %0;" : "+l"(acc) : "l"(a), "l"(b));
}
__device__ __forceinline__ void upk2(unsigned long long v, float& lo, float& hi) {
    asm("mov.b64 {%0, %1}, %2;" : "=f"(lo), "=f"(hi) : "l"(v));
}

// ---------------- kernel 0: params + flag reset ----------------
__global__ void __launch_bounds__(1024) k_params(const float* __restrict__ il,
                                                 const float* __restrict__ tl,
                                                 float* __restrict__ trans_out)
{
    const int w = threadIdx.x >> 5, lane = threadIdx.x & 31;
    for (int i = threadIdx.x; i < BB * NCHUNK; i += 1024) g_flag[i] = 0;
    {
        float vv = tl[w * SS + lane];
        float m = wmax(vv);
        float e = expf(vv - m);
        float s = wsum(e);
        float tr = e / s;
        g_trans[w * SS + lane] = tr;
        trans_out[w * SS + lane] = tr;
        g_logtrans[w * SS + lane] = logf(tr + 1e-10f);
    }
    if (w == 0) {
        float vv = il[lane];
        float m = wmax(vv);
        float e = expf(vv - m);
        float s = wsum(e);
        g_loginit[lane] = logf(e / s + 1e-10f);
    }
}

// ---------------- fused kernel ----------------
// smem floats (65.8 KB -> 3 blocks/SM):
//   SX  @0      [32][128] (4096)     -- stage C overlays W3B[0:4096)
//   WB  @4096   [16][256] (4096)     -- stage C overlays W3B[4096:8192)
//   SH1 @8192   [32][256] (8192)     -- stage B output SH2 overlays (post-sync)
//   MUS @16384  [64]
#define SM_FLOATS 16448
#define MLP_SMEM_BYTES (SM_FLOATS * 4)

__global__ void __launch_bounds__(256, 3) k_fused(
    const float* __restrict__ x,
    const float* __restrict__ W1, const float* __restrict__ b1,
    const float* __restrict__ lng, const float* __restrict__ lnb,
    const float* __restrict__ W2, const float* __restrict__ b2,
    const float* __restrict__ W3, const float* __restrict__ b3,
    float* emis, float* probs, float* ll, float* ps)
{
    // ================= scan blocks (persistent consumers) =================
    if (blockIdx.x < NSCAN) {
        const int wid = threadIdx.x >> 5, j = threadIdx.x & 31;
        if (wid >= 4) return;
        const int b = 2 * (int)blockIdx.x + (wid >> 1);
        const float* em = emis + (size_t)b * TT * SS;

        if ((wid & 1) == 0) {
            // forward scan (lagged-max rescaled) + fused state_probs
            float* pr = probs + (size_t)b * TT * SS;
            float tr[32];
            #pragma unroll
            for (int i = 0; i < 32; i++) tr[i] = g_trans[i * SS + j] + 1e-10f;

            float a = 0.f, m = 0.f, mnext = 0.f;
            for (int c = 0; c < NCHUNK; c++) {
                while (__ldcg(&g_flag[c * BB + b]) == 0) __nanosleep(64);
                __threadfence();
                int t0 = TPB * c;
                const int t1 = t0 + TPB - 1;
                if (c == 0) {
                    a = g_loginit[j] + __ldcg(em + j);
                    m = wmax(a);
                    mnext = m;
                    float e0 = __expf(a - m);
                    float s0 = wsum(e0);
                    pr[j] = __fdividef(e0, s0);
                    t0 = 1;
                }
                float emA = __ldcg(em + (size_t)t0 * SS + j);
                float emB = __ldcg(em + (size_t)((t0 + 1 <= t1) ? t0 + 1 : t1) * SS + j);
                for (int t = t0; t <= t1; t++) {
                    float emv = emA; emA = emB;
                    int tn = (t + 2 <= t1) ? t + 2 : t1;
                    emB = __ldcg(em + (size_t)tn * SS + j);

                    float e = __expf(a - m);
                    float s0 = 0.f, s1 = 0.f, s2 = 0.f, s3 = 0.f;
                    #pragma unroll
                    for (int i = 0; i < 32; i += 4) {
                        s0 = fmaf(__shfl_sync(~0u, e, i    ), tr[i    ], s0);
                        s1 = fmaf(__shfl_sync(~0u, e, i + 1), tr[i + 1], s1);
                        s2 = fmaf(__shfl_sync(~0u, e, i + 2), tr[i + 2], s2);
                        s3 = fmaf(__shfl_sync(~0u, e, i + 3), tr[i + 3], s3);
                    }
                    a = emv + m + __logf((s0 + s1) + (s2 + s3));
                    m = mnext;
                    mnext = wmax(a);
                    float e2 = __expf(a - mnext);
                    float ss = wsum(e2);
                    pr[(size_t)t * SS + j] = __fdividef(e2, ss);
                }
            }
            float e = __expf(a - mnext);
            float sum = wsum(e);
            if (j == 0) ll[b] = mnext + __logf(sum);
        } else {
            // Viterbi scan
            unsigned char* bprow = g_bp + (size_t)b * TT * SS;
            float lt[32];
            #pragma unroll
            for (int i = 0; i < 32; i++) lt[i] = g_logtrans[i * SS + j];

            float v = 0.f;
            for (int c = 0; c < NCHUNK; c++) {
                while (__ldcg(&g_flag[c * BB + b]) == 0) __nanosleep(64);
                __threadfence();
                int t0 = TPB * c;
                const int t1 = t0 + TPB - 1;
                if (c == 0) {
                    v = g_loginit[j] + __ldcg(em + j);
                    t0 = 1;
                }
                float emA = __ldcg(em + (size_t)t0 * SS + j);
                float emB = __ldcg(em + (size_t)((t0 + 1 <= t1) ? t0 + 1 : t1) * SS + j);
                for (int t = t0; t <= t1; t++) {
                    float emv = emA; emA = emB;
                    int tn = (t + 2 <= t1) ? t + 2 : t1;
                    emB = __ldcg(em + (size_t)tn * SS + j);

                    float bv[4]; int bi[4];
                    #pragma unroll
                    for (int cc = 0; cc < 4; cc++) {
                        const int base = cc * 8;
                        float best = __shfl_sync(~0u, v, base) + lt[base];
                        int idx = base;
                        #pragma unroll
                        for (int q = 1; q < 8; q++) {
                            float cand = __shfl_sync(~0u, v, base + q) + lt[base + q];
                            if (cand > best) { best = cand; idx = base + q; }
                        }
                        bv[cc] = best; bi[cc] = idx;
                    }
                    float best = bv[0]; int idx = bi[0];
                    #pragma unroll
                    for (int cc = 1; cc < 4; cc++)
                        if (bv[cc] > best) { best = bv[cc]; idx = bi[cc]; }
                    v = best + emv;
                    bprow[(size_t)t * SS + j] = (unsigned char)idx;
                }
            }
            float bvv = v; int bj = j;
            #pragma unroll
            for (int o = 16; o; o >>= 1) {
                float ov = __shfl_xor_sync(~0u, bvv, o);
                int   oi = __shfl_xor_sync(~0u, bj, o);
                if (ov > bvv || (ov == bvv && oi < bj)) { bvv = ov; bj = oi; }
            }
            if (j == 0) { ps[b] = bvv; g_last[b] = bj; }
        }
        return;
    }

    // ================= MLP blocks (producer), 32 tokens, time-major =================
    extern __shared__ float sm[];
    float* SX  = sm;            // 4096 floats
    float* WB  = sm + 4096;     // 4096 floats
    float* SH1 = sm + 8192;     // 8192 floats; SH2 overlays after stage B
    float* SH2 = sm + 8192;
    float* W3B = sm;            // stage C: overlays SX+WB (8192 floats)
    float* MUS = sm + 16384;

    const int tid = threadIdx.x;
    const int w = tid >> 5, lane = tid & 31;
    const int imlp = blockIdx.x - NSCAN;       // 0..8191
    const int bb = imlp & 31;
    const int cchunk = imlp >> 5;              // 0..255
    const size_t tok0 = (size_t)bb * TT + (size_t)TPB * cchunk;

    {   // load x tile: 32 tokens x 128 = 4096 floats
        const float4* xg = (const float4*)(x + tok0 * IND);
        float4* d = (float4*)SX;
        #pragma unroll
        for (int i = 0; i < 4; i++) d[tid + 256 * i] = xg[tid + 256 * i];
    }

    // accumulators: 4 tokens x 4 column-pairs (cols j0 = 2*lane + 64*u)
    unsigned long long acc2[4][4];
    #pragma unroll
    for (int t = 0; t < 4; t++)
        #pragma unroll
        for (int u = 0; u < 4; u++) acc2[t][u] = 0ull;

    // ---- stage A: h1 = x @ W1 ----
    float4 pf0, pf1, pf2, pf3;
    {
        const float4* wg = (const float4*)W1;
        pf0 = wg[tid]; pf1 = wg[tid + 256]; pf2 = wg[tid + 512]; pf3 = wg[tid + 768];
    }
    for (int kc = 0; kc < IND; kc += 16) {
        __syncthreads();
        {   // natural-layout weight chunk [16][256]
            float4* d = (float4*)WB;
            d[tid] = pf0; d[tid + 256] = pf1; d[tid + 512] = pf2; d[tid + 768] = pf3;
        }
        __syncthreads();
        if (kc + 16 < IND) {
            const float4* wg = (const float4*)(W1 + (size_t)(kc + 16) * HH);
            pf0 = wg[tid]; pf1 = wg[tid + 256]; pf2 = wg[tid + 512]; pf3 = wg[tid + 768];
        }
        #pragma unroll
        for (int k = 0; k < 16; k++) {
            unsigned long long xp[4];
            #pragma unroll
            for (int t = 0; t < 4; t++) {
                float xs = SX[(4 * w + t) * IND + kc + k];   // broadcast
                xp[t] = pk2(xs, xs);
            }
            #pragma unroll
            for (int u = 0; u < 4; u++) {
                unsigned long long wv2 =
                    *(const unsigned long long*)&WB[k * HH + 2 * lane + 64 * u];
                #pragma unroll
                for (int t = 0; t < 4; t++) fma2(acc2[t][u], xp[t], wv2);
            }
        }
    }
    __syncthreads();
    #pragma unroll
    for (int u = 0; u < 4; u++) {
        int j0 = 2 * lane + 64 * u;
        float2 bb2 = *(const float2*)&b1[j0];
        #pragma unroll
        for (int t = 0; t < 4; t++) {
            float lo, hi;
            upk2(acc2[t][u], lo, hi);
            *(float2*)&SH1[(4 * w + t) * HH + j0] = make_float2(lo + bb2.x, hi + bb2.y);
        }
    }
    __syncthreads();

    // ---- LayerNorm stats (warp w: tokens 4w..4w+3) ----
    #pragma unroll
    for (int i = 0; i < 4; i++) {
        int t = 4 * w + i;
        float s = 0.f, ss = 0.f;
        #pragma unroll
        for (int u = 0; u < 8; u++) {
            float v = SH1[t * HH + lane + 32 * u];
            s += v; ss = fmaf(v, v, ss);
        }
        s = wsum(s); ss = wsum(ss);
        if (lane == 0) {
            float mu = s * (1.f / HH);
            float var = ss * (1.f / HH) - mu * mu;
            MUS[2 * t] = mu;
            MUS[2 * t + 1] = rsqrtf(var + 1e-5f);
        }
    }
    __syncthreads();

    // ---- LN transform + GELU in place (thread = column tid) ----
    {
        float gv = lng[tid], bv = lnb[tid];
        #pragma unroll 8
        for (int t = 0; t < TPB; t++) {
            float v = SH1[t * HH + tid];
            v = (v - MUS[2 * t]) * MUS[2 * t + 1] * gv + bv;
            SH1[t * HH + tid] = gelu_exact(v);
        }
    }

    // ---- stage B: h2 = gelu(g1 @ W2 + b2) ----
    #pragma unroll
    for (int t = 0; t < 4; t++)
        #pragma unroll
        for (int u = 0; u < 4; u++) acc2[t][u] = 0ull;

    {
        const float4* wg = (const float4*)W2;
        pf0 = wg[tid]; pf1 = wg[tid + 256]; pf2 = wg[tid + 512]; pf3 = wg[tid + 768];
    }
    for (int kc = 0; kc < HH; kc += 16) {
        __syncthreads();
        {
            float4* d = (float4*)WB;
            d[tid] = pf0; d[tid + 256] = pf1; d[tid + 512] = pf2; d[tid + 768] = pf3;
        }
        __syncthreads();
        if (kc + 16 < HH) {
            const float4* wg = (const float4*)(W2 + (size_t)(kc + 16) * HH);
            pf0 = wg[tid]; pf1 = wg[tid + 256]; pf2 = wg[tid + 512]; pf3 = wg[tid + 768];
        }
        #pragma unroll
        for (int k = 0; k < 16; k++) {
            unsigned long long xp[4];
            #pragma unroll
            for (int t = 0; t < 4; t++) {
                float xs = SH1[(4 * w + t) * HH + kc + k];   // broadcast
                xp[t] = pk2(xs, xs);
            }
            #pragma unroll
            for (int u = 0; u < 4; u++) {
                unsigned long long wv2 =
                    *(const unsigned long long*)&WB[k * HH + 2 * lane + 64 * u];
                #pragma unroll
                for (int t = 0; t < 4; t++) fma2(acc2[t][u], xp[t], wv2);
            }
        }
    }
    __syncthreads();   // all SH1 reads done -> safe to overlay with SH2
    #pragma unroll
    for (int u = 0; u < 4; u++) {
        int j0 = 2 * lane + 64 * u;
        float2 bb2 = *(const float2*)&b2[j0];
        #pragma unroll
        for (int t = 0; t < 4; t++) {
            float lo, hi;
            upk2(acc2[t][u], lo, hi);
            *(float2*)&SH2[(4 * w + t) * HH + j0] =
                make_float2(gelu_exact(lo + bb2.x), gelu_exact(hi + bb2.y));
        }
    }
    __syncthreads();   // WB/SX dead -> W3B region valid

    // ---- stage C: logits = h2 @ W3 + b3 -> log_softmax ----
    {
        const float4* wg = (const float4*)W3;
        float4* d = (float4*)W3B;
        #pragma unroll
        for (int i = 0; i < 8; i++) d[tid + 256 * i] = wg[tid + 256 * i];
    }
    __syncthreads();

    // token pairs p: (4w+2p, 4w+2p+1); lane = output state
    unsigned long long acc3[2] = {0ull, 0ull};
    for (int k4 = 0; k4 < HH / 4; k4++) {
        float4 xa[4];
        #pragma unroll
        for (int t = 0; t < 4; t++)
            xa[t] = *(const float4*)&SH2[(4 * w + t) * HH + 4 * k4];   // broadcast
        #pragma unroll
        for (int q = 0; q < 4; q++) {
            float wv = W3B[(4 * k4 + q) * SS + lane];
            unsigned long long wv2 = pk2(wv, wv);
            #pragma unroll
            for (int p = 0; p < 2; p++) {
                float x0 = q == 0 ? xa[2 * p].x : q == 1 ? xa[2 * p].y : q == 2 ? xa[2 * p].z : xa[2 * p].w;
                float x1 = q == 0 ? xa[2 * p + 1].x : q == 1 ? xa[2 * p + 1].y : q == 2 ? xa[2 * p + 1].z : xa[2 * p + 1].w;
                fma2(acc3[p], pk2(x0, x1), wv2);
            }
        }
    }
    float bbv = b3[lane];
    #pragma unroll
    for (int p = 0; p < 2; p++) {
        float v0, v1;
        upk2(acc3[p], v0, v1);
        #pragma unroll
        for (int h = 0; h < 2; h++) {
            float v = (h == 0 ? v0 : v1) + bbv;
            float m = wmax(v);
            float e = expf(v - m);
            float s = wsum(e);
            emis[(tok0 + 4 * w + 2 * p + h) * SS + lane] = v - m - logf(s);
        }
    }

    // ---- publish chunk ----
    __threadfence();
    __syncthreads();
    if (tid == 0) atomicExch(&g_flag[imlp], 1);
}

// ---------------- backtrace: segment composition ----------------
__global__ void __launch_bounds__(1024) k_backtrace(float* __restrict__ bp_out)
{
    __shared__ int comp[32][32];
    __shared__ int entry_s[32];
    const int b = blockIdx.x;
    const int seg = threadIdx.x >> 5, e = threadIdx.x & 31;
    const unsigned char* bp = g_bp + (size_t)b * TT * SS;
    const int tTop = seg * 256 + 255;

    int st = e;
    for (int t = tTop; t >= seg * 256 + 1; t--)
        st = bp[(size_t)t * SS + st];
    comp[seg][e] = st;
    __syncthreads();

    if (threadIdx.x == 0) {
        int cur = g_last[b];
        for (int s = 31; s >= 0; s--) {
            entry_s[s] = cur;
            int ex = comp[s][cur];
            if (s > 0) cur = bp[(size_t)(256 * s) * SS + ex];
        }
    }
    __syncthreads();

    if (e == 0) {
        int cur = entry_s[seg];
        float* o = bp_out + (size_t)b * TT;
        o[tTop] = (float)cur;
        for (int t = tTop; t >= seg * 256 + 1; t--) {
            cur = bp[(size_t)t * SS + cur];
            o[t - 1] = (float)cur;
        }
    }
}

extern "C" void kernel_launch(void* const* d_in, const int* in_sizes, int n_in,
                              void* d_out, int out_size)
{
    const float* x   = (const float*)d_in[0];
    const float* il  = (const float*)d_in[1];
    const float* tl  = (const float*)d_in[2];
    const float* W1  = (const float*)d_in[3];
    const float* b1  = (const float*)d_in[4];
    const float* lng = (const float*)d_in[5];
    const float* lnb = (const float*)d_in[6];
    const float* W2  = (const float*)d_in[7];
    const float* b2  = (const float*)d_in[8];
    const float* W3  = (const float*)d_in[9];
    const float* b3  = (const float*)d_in[10];
    float* out = (float*)d_out;

    static bool attr_done = false;
    if (!attr_done) {
        cudaFuncSetAttribute(k_fused, cudaFuncAttributeMaxDynamicSharedMemorySize, MLP_SMEM_BYTES);
        attr_done = true;
    }

    k_params<<<1, 1024>>>(il, tl, out + TRANS_OFF);
    k_fused<<<NSCAN + NMLP, 256, MLP_SMEM_BYTES>>>(x, W1, b1, lng, lnb, W2, b2, W3, b3,
                                                   out, out + PROBS_OFF,
                                                   out + LL_OFF, out + PS_OFF);
    k_backtrace<<<BB, 1024>>>(out + BP_OFF);
}

// round 8
// speedup vs baseline: 1.1006x; 1.1006x over previous
#include <cuda_runtime.h>
#include <math.h>

#define BB   32
#define TT   8192
#define SS   32
#define IND  128
#define HH   256
#define NTOK (BB*TT)
#define TPB  64                 // tokens per MLP block
#define NMLP (NTOK/TPB)         // 4096
#define NCHUNK (TT/TPB)         // 128 chunks per batch
#define NSCAN 16                // scan blocks (2 batches each)

// output section offsets (floats): emissions, state_probs, ll, trans, best_path, path_score
#define PROBS_OFF  8388608L
#define LL_OFF     16777216L
#define TRANS_OFF  16777248L
#define BP_OFF     16778272L
#define PS_OFF     17040416L

__device__ unsigned char g_bp[(size_t)NTOK * SS];
__device__ float g_trans[SS * SS];
__device__ float g_logtrans[SS * SS];
__device__ float g_loginit[SS];
__device__ int   g_last[BB];
__device__ int   g_flag[BB * NCHUNK];

__device__ __forceinline__ float gelu_exact(float v) {
    return 0.5f * v * (1.0f + erff(v * 0.70710678118654752440f));
}
__device__ __forceinline__ float wmax(float v) {
    #pragma unroll
    for (int o = 16; o; o >>= 1) v = fmaxf(v, __shfl_xor_sync(~0u, v, o));
    return v;
}
__device__ __forceinline__ float wsum(float v) {
    #pragma unroll
    for (int o = 16; o; o >>= 1) v += __shfl_xor_sync(~0u, v, o);
    return v;
}
__device__ __forceinline__ unsigned long long pk2(float lo, float hi) {
    unsigned long long r;
    asm("mov.b64 %0, {%1, %2};" : "=l"(r) : "f"(lo), "f"(hi));
    return r;
}
__device__ __forceinline__ void fma2(unsigned long long& acc, unsigned long long a,
                                     unsigned long long b) {
    asm("fma.rn.f32x2 %0, %1, %2, %0;" : "+l"(acc) : "l"(a), "l"(b));
}
__device__ __forceinline__ void upk2(unsigned long long v, float& lo, float& hi) {
    asm("mov.b64 {%0, %1}, %2;" : "=f"(lo), "=f"(hi) : "l"(v));
}

// ---------------- kernel 0: params + flag reset ----------------
__global__ void __launch_bounds__(1024) k_params(const float* __restrict__ il,
                                                 const float* __restrict__ tl,
                                                 float* __restrict__ trans_out)
{
    const int w = threadIdx.x >> 5, lane = threadIdx.x & 31;
    for (int i = threadIdx.x; i < BB * NCHUNK; i += 1024) g_flag[i] = 0;
    {
        float vv = tl[w * SS + lane];
        float m = wmax(vv);
        float e = expf(vv - m);
        float s = wsum(e);
        float tr = e / s;
        g_trans[w * SS + lane] = tr;
        trans_out[w * SS + lane] = tr;
        g_logtrans[w * SS + lane] = logf(tr + 1e-10f);
    }
    if (w == 0) {
        float vv = il[lane];
        float m = wmax(vv);
        float e = expf(vv - m);
        float s = wsum(e);
        g_loginit[lane] = logf(e / s + 1e-10f);
    }
}

// ---------------- fused kernel ----------------
// smem floats (26752 = 104.5 KB -> 2 blocks/SM):
//   SH1 @0      [64][256] (16384)   -- SH2 overlays after stage B (post-sync)
//   WB  @16384  [8][256]  (2048)    -- weight k-chunk (8 rows)
//   SX  @18432  [64][128] (8192)    -- stage C overlays as W3B [256][32]
//   MUS @26624  [128]
#define SM_FLOATS 26752
#define MLP_SMEM_BYTES (SM_FLOATS * 4)

__global__ void __launch_bounds__(256, 2) k_fused(
    const float* __restrict__ x,
    const float* __restrict__ W1, const float* __restrict__ b1,
    const float* __restrict__ lng, const float* __restrict__ lnb,
    const float* __restrict__ W2, const float* __restrict__ b2,
    const float* __restrict__ W3, const float* __restrict__ b3,
    float* emis, float* probs, float* ll, float* ps)
{
    // ================= scan blocks (persistent consumers) =================
    if (blockIdx.x < NSCAN) {
        const int wid = threadIdx.x >> 5, j = threadIdx.x & 31;
        if (wid >= 4) return;
        const int b = 2 * (int)blockIdx.x + (wid >> 1);
        const float* em = emis + (size_t)b * TT * SS;

        if ((wid & 1) == 0) {
            // forward scan (lagged-max rescaled) + fused state_probs
            float* pr = probs + (size_t)b * TT * SS;
            float tr[32];
            #pragma unroll
            for (int i = 0; i < 32; i++) tr[i] = g_trans[i * SS + j] + 1e-10f;

            float a = 0.f, m = 0.f, mnext = 0.f;
            for (int c = 0; c < NCHUNK; c++) {
                while (__ldcg(&g_flag[c * BB + b]) == 0) __nanosleep(64);
                __threadfence();
                int t0 = TPB * c;
                const int t1 = t0 + TPB - 1;
                if (c == 0) {
                    a = g_loginit[j] + __ldcg(em + j);
                    m = wmax(a);
                    mnext = m;
                    float e0 = __expf(a - m);
                    float s0 = wsum(e0);
                    pr[j] = __fdividef(e0, s0);
                    t0 = 1;
                }
                float emA = __ldcg(em + (size_t)t0 * SS + j);
                float emB = __ldcg(em + (size_t)((t0 + 1 <= t1) ? t0 + 1 : t1) * SS + j);
                for (int t = t0; t <= t1; t++) {
                    float emv = emA; emA = emB;
                    int tn = (t + 2 <= t1) ? t + 2 : t1;
                    emB = __ldcg(em + (size_t)tn * SS + j);

                    float e = __expf(a - m);
                    float s0 = 0.f, s1 = 0.f, s2 = 0.f, s3 = 0.f;
                    #pragma unroll
                    for (int i = 0; i < 32; i += 4) {
                        s0 = fmaf(__shfl_sync(~0u, e, i    ), tr[i    ], s0);
                        s1 = fmaf(__shfl_sync(~0u, e, i + 1), tr[i + 1], s1);
                        s2 = fmaf(__shfl_sync(~0u, e, i + 2), tr[i + 2], s2);
                        s3 = fmaf(__shfl_sync(~0u, e, i + 3), tr[i + 3], s3);
                    }
                    a = emv + m + __logf((s0 + s1) + (s2 + s3));
                    m = mnext;
                    mnext = wmax(a);
                    float e2 = __expf(a - mnext);
                    float ss = wsum(e2);
                    pr[(size_t)t * SS + j] = __fdividef(e2, ss);
                }
            }
            float e = __expf(a - mnext);
            float sum = wsum(e);
            if (j == 0) ll[b] = mnext + __logf(sum);
        } else {
            // Viterbi scan
            unsigned char* bprow = g_bp + (size_t)b * TT * SS;
            float lt[32];
            #pragma unroll
            for (int i = 0; i < 32; i++) lt[i] = g_logtrans[i * SS + j];

            float v = 0.f;
            for (int c = 0; c < NCHUNK; c++) {
                while (__ldcg(&g_flag[c * BB + b]) == 0) __nanosleep(64);
                __threadfence();
                int t0 = TPB * c;
                const int t1 = t0 + TPB - 1;
                if (c == 0) {
                    v = g_loginit[j] + __ldcg(em + j);
                    t0 = 1;
                }
                float emA = __ldcg(em + (size_t)t0 * SS + j);
                float emB = __ldcg(em + (size_t)((t0 + 1 <= t1) ? t0 + 1 : t1) * SS + j);
                for (int t = t0; t <= t1; t++) {
                    float emv = emA; emA = emB;
                    int tn = (t + 2 <= t1) ? t + 2 : t1;
                    emB = __ldcg(em + (size_t)tn * SS + j);

                    float bv[4]; int bi[4];
                    #pragma unroll
                    for (int cc = 0; cc < 4; cc++) {
                        const int base = cc * 8;
                        float best = __shfl_sync(~0u, v, base) + lt[base];
                        int idx = base;
                        #pragma unroll
                        for (int q = 1; q < 8; q++) {
                            float cand = __shfl_sync(~0u, v, base + q) + lt[base + q];
                            if (cand > best) { best = cand; idx = base + q; }
                        }
                        bv[cc] = best; bi[cc] = idx;
                    }
                    float best = bv[0]; int idx = bi[0];
                    #pragma unroll
                    for (int cc = 1; cc < 4; cc++)
                        if (bv[cc] > best) { best = bv[cc]; idx = bi[cc]; }
                    v = best + emv;
                    bprow[(size_t)t * SS + j] = (unsigned char)idx;
                }
            }
            float bvv = v; int bj = j;
            #pragma unroll
            for (int o = 16; o; o >>= 1) {
                float ov = __shfl_xor_sync(~0u, bvv, o);
                int   oi = __shfl_xor_sync(~0u, bj, o);
                if (ov > bvv || (ov == bvv && oi < bj)) { bvv = ov; bj = oi; }
            }
            if (j == 0) { ps[b] = bvv; g_last[b] = bj; }
        }
        return;
    }

    // ================= MLP blocks (producer), 64 tokens, time-major =================
    extern __shared__ float sm[];
    float* SH1 = sm;              // 16384 floats; SH2 overlays post-stage-B
    float* SH2 = sm;
    float* WB  = sm + 16384;      // 2048 floats (8 rows x 256)
    float* SX  = sm + 18432;      // 8192 floats; W3B overlays in stage C
    float* W3B = sm + 18432;
    float* MUS = sm + 26624;

    const int tid = threadIdx.x;
    const int w = tid >> 5, lane = tid & 31;
    const int imlp = blockIdx.x - NSCAN;       // 0..4095
    const int cchunk = imlp >> 5;              // 0..127
    const int bb = imlp & 31;
    const size_t tok0 = (size_t)bb * TT + (size_t)TPB * cchunk;

    {   // load x tile: 64 tokens x 128 = 8192 floats
        const float4* xg = (const float4*)(x + tok0 * IND);
        float4* d = (float4*)SX;
        #pragma unroll
        for (int i = 0; i < 8; i++) d[tid + 256 * i] = xg[tid + 256 * i];
    }

    // accumulators: 8 tokens x 4 column-pairs (cols j0 = 2*lane + 64*u)
    unsigned long long acc2[8][4];
    #pragma unroll
    for (int t = 0; t < 8; t++)
        #pragma unroll
        for (int u = 0; u < 4; u++) acc2[t][u] = 0ull;

    // ---- stage A: h1 = x @ W1 (8-row weight chunks) ----
    float4 pf0, pf1;
    {
        const float4* wg = (const float4*)W1;
        pf0 = wg[tid]; pf1 = wg[tid + 256];
    }
    for (int kc = 0; kc < IND; kc += 8) {
        __syncthreads();
        {
            float4* d = (float4*)WB;
            d[tid] = pf0; d[tid + 256] = pf1;
        }
        __syncthreads();
        if (kc + 8 < IND) {
            const float4* wg = (const float4*)(W1 + (size_t)(kc + 8) * HH);
            pf0 = wg[tid]; pf1 = wg[tid + 256];
        }
        #pragma unroll
        for (int k = 0; k < 8; k++) {
            unsigned long long xp[8];
            #pragma unroll
            for (int t = 0; t < 8; t++) {
                float xs = SX[(8 * w + t) * IND + kc + k];   // broadcast
                xp[t] = pk2(xs, xs);
            }
            #pragma unroll
            for (int u = 0; u < 4; u++) {
                unsigned long long wv2 =
                    *(const unsigned long long*)&WB[k * HH + 2 * lane + 64 * u];
                #pragma unroll
                for (int t = 0; t < 8; t++) fma2(acc2[t][u], xp[t], wv2);
            }
        }
    }
    __syncthreads();
    #pragma unroll
    for (int u = 0; u < 4; u++) {
        int j0 = 2 * lane + 64 * u;
        float2 bb2 = *(const float2*)&b1[j0];
        #pragma unroll
        for (int t = 0; t < 8; t++) {
            float lo, hi;
            upk2(acc2[t][u], lo, hi);
            *(float2*)&SH1[(8 * w + t) * HH + j0] = make_float2(lo + bb2.x, hi + bb2.y);
        }
    }
    __syncthreads();

    // ---- LayerNorm stats (warp w: tokens 8w..8w+7) ----
    #pragma unroll
    for (int i = 0; i < 8; i++) {
        int t = 8 * w + i;
        float s = 0.f, ss = 0.f;
        #pragma unroll
        for (int u = 0; u < 8; u++) {
            float v = SH1[t * HH + lane + 32 * u];
            s += v; ss = fmaf(v, v, ss);
        }
        s = wsum(s); ss = wsum(ss);
        if (lane == 0) {
            float mu = s * (1.f / HH);
            float var = ss * (1.f / HH) - mu * mu;
            MUS[2 * t] = mu;
            MUS[2 * t + 1] = rsqrtf(var + 1e-5f);
        }
    }
    __syncthreads();

    // ---- LN transform + GELU in place ----
    {
        float gv = lng[tid], bv = lnb[tid];
        #pragma unroll 8
        for (int t = 0; t < TPB; t++) {
            float v = SH1[t * HH + tid];
            v = (v - MUS[2 * t]) * MUS[2 * t + 1] * gv + bv;
            SH1[t * HH + tid] = gelu_exact(v);
        }
    }

    // ---- stage B: h2 = gelu(g1 @ W2 + b2) ----
    #pragma unroll
    for (int t = 0; t < 8; t++)
        #pragma unroll
        for (int u = 0; u < 4; u++) acc2[t][u] = 0ull;

    {
        const float4* wg = (const float4*)W2;
        pf0 = wg[tid]; pf1 = wg[tid + 256];
    }
    for (int kc = 0; kc < HH; kc += 8) {
        __syncthreads();
        {
            float4* d = (float4*)WB;
            d[tid] = pf0; d[tid + 256] = pf1;
        }
        __syncthreads();
        if (kc + 8 < HH) {
            const float4* wg = (const float4*)(W2 + (size_t)(kc + 8) * HH);
            pf0 = wg[tid]; pf1 = wg[tid + 256];
        }
        #pragma unroll
        for (int k = 0; k < 8; k++) {
            unsigned long long xp[8];
            #pragma unroll
            for (int t = 0; t < 8; t++) {
                float xs = SH1[(8 * w + t) * HH + kc + k];   // broadcast
                xp[t] = pk2(xs, xs);
            }
            #pragma unroll
            for (int u = 0; u < 4; u++) {
                unsigned long long wv2 =
                    *(const unsigned long long*)&WB[k * HH + 2 * lane + 64 * u];
                #pragma unroll
                for (int t = 0; t < 8; t++) fma2(acc2[t][u], xp[t], wv2);
            }
        }
    }
    __syncthreads();   // all SH1 reads complete -> safe to overlay with SH2
    #pragma unroll
    for (int u = 0; u < 4; u++) {
        int j0 = 2 * lane + 64 * u;
        float2 bb2 = *(const float2*)&b2[j0];
        #pragma unroll
        for (int t = 0; t < 8; t++) {
            float lo, hi;
            upk2(acc2[t][u], lo, hi);
            *(float2*)&SH2[(8 * w + t) * HH + j0] =
                make_float2(gelu_exact(lo + bb2.x), gelu_exact(hi + bb2.y));
        }
    }
    __syncthreads();   // SX dead -> W3B region valid

    // ---- stage C: logits = h2 @ W3 + b3 -> log_softmax ----
    {
        const float4* wg = (const float4*)W3;
        float4* d = (float4*)W3B;
        #pragma unroll
        for (int i = 0; i < 8; i++) d[tid + 256 * i] = wg[tid + 256 * i];
    }
    __syncthreads();

    // token pairs p: (8w+2p, 8w+2p+1); lane = output state
    unsigned long long acc3[4] = {0ull, 0ull, 0ull, 0ull};
    for (int k4 = 0; k4 < HH / 4; k4++) {
        float4 xa[8];
        #pragma unroll
        for (int t = 0; t < 8; t++)
            xa[t] = *(const float4*)&SH2[(8 * w + t) * HH + 4 * k4];   // broadcast
        #pragma unroll
        for (int q = 0; q < 4; q++) {
            float wv = W3B[(4 * k4 + q) * SS + lane];
            unsigned long long wv2 = pk2(wv, wv);
            #pragma unroll
            for (int p = 0; p < 4; p++) {
                float x0 = q == 0 ? xa[2 * p].x : q == 1 ? xa[2 * p].y : q == 2 ? xa[2 * p].z : xa[2 * p].w;
                float x1 = q == 0 ? xa[2 * p + 1].x : q == 1 ? xa[2 * p + 1].y : q == 2 ? xa[2 * p + 1].z : xa[2 * p + 1].w;
                fma2(acc3[p], pk2(x0, x1), wv2);
            }
        }
    }
    float bbv = b3[lane];
    #pragma unroll
    for (int p = 0; p < 4; p++) {
        float v0, v1;
        upk2(acc3[p], v0, v1);
        #pragma unroll
        for (int h = 0; h < 2; h++) {
            float v = (h == 0 ? v0 : v1) + bbv;
            float m = wmax(v);
            float e = expf(v - m);
            float s = wsum(e);
            emis[(tok0 + 8 * w + 2 * p + h) * SS + lane] = v - m - logf(s);
        }
    }

    // ---- publish chunk ----
    __threadfence();
    __syncthreads();
    if (tid == 0) atomicExch(&g_flag[imlp], 1);
}

// ---------------- backtrace: segment composition ----------------
__global__ void __launch_bounds__(1024) k_backtrace(float* __restrict__ bp_out)
{
    __shared__ int comp[32][32];
    __shared__ int entry_s[32];
    const int b = blockIdx.x;
    const int seg = threadIdx.x >> 5, e = threadIdx.x & 31;
    const unsigned char* bp = g_bp + (size_t)b * TT * SS;
    const int tTop = seg * 256 + 255;

    int st = e;
    for (int t = tTop; t >= seg * 256 + 1; t--)
        st = bp[(size_t)t * SS + st];
    comp[seg][e] = st;
    __syncthreads();

    if (threadIdx.x == 0) {
        int cur = g_last[b];
        for (int s = 31; s >= 0; s--) {
            entry_s[s] = cur;
            int ex = comp[s][cur];
            if (s > 0) cur = bp[(size_t)(256 * s) * SS + ex];
        }
    }
    __syncthreads();

    if (e == 0) {
        int cur = entry_s[seg];
        float* o = bp_out + (size_t)b * TT;
        o[tTop] = (float)cur;
        for (int t = tTop; t >= seg * 256 + 1; t--) {
            cur = bp[(size_t)t * SS + cur];
            o[t - 1] = (float)cur;
        }
    }
}

extern "C" void kernel_launch(void* const* d_in, const int* in_sizes, int n_in,
                              void* d_out, int out_size)
{
    const float* x   = (const float*)d_in[0];
    const float* il  = (const float*)d_in[1];
    const float* tl  = (const float*)d_in[2];
    const float* W1  = (const float*)d_in[3];
    const float* b1  = (const float*)d_in[4];
    const float* lng = (const float*)d_in[5];
    const float* lnb = (const float*)d_in[6];
    const float* W2  = (const float*)d_in[7];
    const float* b2  = (const float*)d_in[8];
    const float* W3  = (const float*)d_in[9];
    const float* b3  = (const float*)d_in[10];
    float* out = (float*)d_out;

    static bool attr_done = false;
    if (!attr_done) {
        cudaFuncSetAttribute(k_fused, cudaFuncAttributeMaxDynamicSharedMemorySize, MLP_SMEM_BYTES);
        attr_done = true;
    }

    k_params<<<1, 1024>>>(il, tl, out + TRANS_OFF);
    k_fused<<<NSCAN + NMLP, 256, MLP_SMEM_BYTES>>>(x, W1, b1, lng, lnb, W2, b2, W3, b3,
                                                   out, out + PROBS_OFF,
                                                   out + LL_OFF, out + PS_OFF);
    k_backtrace<<<BB, 1024>>>(out + BP_OFF);
}

// round 9
// speedup vs baseline: 1.1105x; 1.0090x over previous
#include <cuda_runtime.h>
#include <math.h>

#define BB   32
#define TT   8192
#define SS   32
#define IND  128
#define HH   256
#define NTOK (BB*TT)
#define TPB  64                 // tokens per MLP block
#define NMLP (NTOK/TPB)         // 4096
#define NCHUNK (TT/TPB)         // 128 chunks per batch
#define NSCAN 16                // scan blocks (2 batches each)

// output section offsets (floats): emissions, state_probs, ll, trans, best_path, path_score
#define PROBS_OFF  8388608L
#define LL_OFF     16777216L
#define TRANS_OFF  16777248L
#define BP_OFF     16778272L
#define PS_OFF     17040416L

__device__ unsigned char g_bp[(size_t)NTOK * SS];
__device__ float g_trans[SS * SS];
__device__ float g_logtrans[SS * SS];
__device__ float g_loginit[SS];
__device__ int   g_last[BB];
__device__ int   g_flag[BB * NCHUNK];

__device__ __forceinline__ float gelu_exact(float v) {
    return 0.5f * v * (1.0f + erff(v * 0.70710678118654752440f));
}
__device__ __forceinline__ float wmax(float v) {
    #pragma unroll
    for (int o = 16; o; o >>= 1) v = fmaxf(v, __shfl_xor_sync(~0u, v, o));
    return v;
}
__device__ __forceinline__ float wsum(float v) {
    #pragma unroll
    for (int o = 16; o; o >>= 1) v += __shfl_xor_sync(~0u, v, o);
    return v;
}
__device__ __forceinline__ unsigned long long pk2(float lo, float hi) {
    unsigned long long r;
    asm("mov.b64 %0, {%1, %2};" : "=l"(r) : "f"(lo), "f"(hi));
    return r;
}
__device__ __forceinline__ void fma2(unsigned long long& acc, unsigned long long a,
                                     unsigned long long b) {
    asm("fma.rn.f32x2 %0, %1, %2, %0;" : "+l"(acc) : "l"(a), "l"(b));
}
__device__ __forceinline__ void upk2(unsigned long long v, float& lo, float& hi) {
    asm("mov.b64 {%0, %1}, %2;" : "=f"(lo), "=f"(hi) : "l"(v));
}

// ---------------- kernel 0: params + flag reset ----------------
__global__ void __launch_bounds__(1024) k_params(const float* __restrict__ il,
                                                 const float* __restrict__ tl,
                                                 float* __restrict__ trans_out)
{
    const int w = threadIdx.x >> 5, lane = threadIdx.x & 31;
    for (int i = threadIdx.x; i < BB * NCHUNK; i += 1024) g_flag[i] = 0;
    {
        float vv = tl[w * SS + lane];
        float m = wmax(vv);
        float e = expf(vv - m);
        float s = wsum(e);
        float tr = e / s;
        g_trans[w * SS + lane] = tr;
        trans_out[w * SS + lane] = tr;
        g_logtrans[w * SS + lane] = logf(tr + 1e-10f);
    }
    if (w == 0) {
        float vv = il[lane];
        float m = wmax(vv);
        float e = expf(vv - m);
        float s = wsum(e);
        g_loginit[lane] = logf(e / s + 1e-10f);
    }
}

// ---------------- fused kernel ----------------
// smem floats (24704 = 96.5 KB -> 2 blocks/SM):
//   SH1/SH2 @0      [64][256] (16384)  (SH2 overlays SH1 post-stage-B)
//   WB0     @16384  [8][256]  (2048)
//   WB1     @18432  [8][256]  (2048)
//   spare   @20480  (4096)             -- stage C: W3B = [16384,24576) contiguous
//   MUS     @24576  [128]
#define SM_FLOATS 24704
#define MLP_SMEM_BYTES (SM_FLOATS * 4)

__global__ void __launch_bounds__(256, 2) k_fused(
    const float* __restrict__ x,
    const float* __restrict__ W1, const float* __restrict__ b1,
    const float* __restrict__ lng, const float* __restrict__ lnb,
    const float* __restrict__ W2, const float* __restrict__ b2,
    const float* __restrict__ W3, const float* __restrict__ b3,
    float* emis, float* probs, float* ll, float* ps)
{
    // ================= scan blocks (persistent consumers) =================
    if (blockIdx.x < NSCAN) {
        const int wid = threadIdx.x >> 5, j = threadIdx.x & 31;
        if (wid >= 4) return;
        const int b = 2 * (int)blockIdx.x + (wid >> 1);
        const float* em = emis + (size_t)b * TT * SS;

        if ((wid & 1) == 0) {
            // forward scan (lagged-max rescaled) + fused state_probs
            float* pr = probs + (size_t)b * TT * SS;
            float tr[32];
            #pragma unroll
            for (int i = 0; i < 32; i++) tr[i] = g_trans[i * SS + j] + 1e-10f;

            float a = 0.f, m = 0.f, mnext = 0.f;
            for (int c = 0; c < NCHUNK; c++) {
                while (__ldcg(&g_flag[c * BB + b]) == 0) __nanosleep(64);
                __threadfence();
                int t0 = TPB * c;
                const int t1 = t0 + TPB - 1;
                if (c == 0) {
                    a = g_loginit[j] + __ldcg(em + j);
                    m = wmax(a);
                    mnext = m;
                    float e0 = __expf(a - m);
                    float s0 = wsum(e0);
                    pr[j] = __fdividef(e0, s0);
                    t0 = 1;
                }
                float emA = __ldcg(em + (size_t)t0 * SS + j);
                float emB = __ldcg(em + (size_t)((t0 + 1 <= t1) ? t0 + 1 : t1) * SS + j);
                for (int t = t0; t <= t1; t++) {
                    float emv = emA; emA = emB;
                    int tn = (t + 2 <= t1) ? t + 2 : t1;
                    emB = __ldcg(em + (size_t)tn * SS + j);

                    float e = __expf(a - m);
                    float s0 = 0.f, s1 = 0.f, s2 = 0.f, s3 = 0.f;
                    #pragma unroll
                    for (int i = 0; i < 32; i += 4) {
                        s0 = fmaf(__shfl_sync(~0u, e, i    ), tr[i    ], s0);
                        s1 = fmaf(__shfl_sync(~0u, e, i + 1), tr[i + 1], s1);
                        s2 = fmaf(__shfl_sync(~0u, e, i + 2), tr[i + 2], s2);
                        s3 = fmaf(__shfl_sync(~0u, e, i + 3), tr[i + 3], s3);
                    }
                    a = emv + m + __logf((s0 + s1) + (s2 + s3));
                    m = mnext;
                    mnext = wmax(a);
                    float e2 = __expf(a - mnext);
                    float ss = wsum(e2);
                    pr[(size_t)t * SS + j] = __fdividef(e2, ss);
                }
            }
            float e = __expf(a - mnext);
            float sum = wsum(e);
            if (j == 0) ll[b] = mnext + __logf(sum);
        } else {
            // Viterbi scan
            unsigned char* bprow = g_bp + (size_t)b * TT * SS;
            float lt[32];
            #pragma unroll
            for (int i = 0; i < 32; i++) lt[i] = g_logtrans[i * SS + j];

            float v = 0.f;
            for (int c = 0; c < NCHUNK; c++) {
                while (__ldcg(&g_flag[c * BB + b]) == 0) __nanosleep(64);
                __threadfence();
                int t0 = TPB * c;
                const int t1 = t0 + TPB - 1;
                if (c == 0) {
                    v = g_loginit[j] + __ldcg(em + j);
                    t0 = 1;
                }
                float emA = __ldcg(em + (size_t)t0 * SS + j);
                float emB = __ldcg(em + (size_t)((t0 + 1 <= t1) ? t0 + 1 : t1) * SS + j);
                for (int t = t0; t <= t1; t++) {
                    float emv = emA; emA = emB;
                    int tn = (t + 2 <= t1) ? t + 2 : t1;
                    emB = __ldcg(em + (size_t)tn * SS + j);

                    float bv[4]; int bi[4];
                    #pragma unroll
                    for (int cc = 0; cc < 4; cc++) {
                        const int base = cc * 8;
                        float best = __shfl_sync(~0u, v, base) + lt[base];
                        int idx = base;
                        #pragma unroll
                        for (int q = 1; q < 8; q++) {
                            float cand = __shfl_sync(~0u, v, base + q) + lt[base + q];
                            if (cand > best) { best = cand; idx = base + q; }
                        }
                        bv[cc] = best; bi[cc] = idx;
                    }
                    float best = bv[0]; int idx = bi[0];
                    #pragma unroll
                    for (int cc = 1; cc < 4; cc++)
                        if (bv[cc] > best) { best = bv[cc]; idx = bi[cc]; }
                    v = best + emv;
                    bprow[(size_t)t * SS + j] = (unsigned char)idx;
                }
            }
            float bvv = v; int bj = j;
            #pragma unroll
            for (int o = 16; o; o >>= 1) {
                float ov = __shfl_xor_sync(~0u, bvv, o);
                int   oi = __shfl_xor_sync(~0u, bj, o);
                if (ov > bvv || (ov == bvv && oi < bj)) { bvv = ov; bj = oi; }
            }
            if (j == 0) { ps[b] = bvv; g_last[b] = bj; }
        }
        return;
    }

    // ================= MLP blocks (producer), 64 tokens, time-major =================
    extern __shared__ float sm[];
    float* SH1 = sm;              // 16384 floats; SH2 overlays post-stage-B
    float* SH2 = sm;
    float* WB0 = sm + 16384;      // 2048 floats
    float* WB1 = sm + 18432;      // 2048 floats
    float* W3B = sm + 16384;      // stage C: 8192 floats [16384,24576)
    float* MUS = sm + 24576;

    const int tid = threadIdx.x;
    const int w = tid >> 5, lane = tid & 31;
    const int imlp = blockIdx.x - NSCAN;       // 0..4095
    const int cchunk = imlp >> 5;              // 0..127
    const int bb = imlp & 31;
    const size_t tok0 = (size_t)bb * TT + (size_t)TPB * cchunk;
    const float* xg = x + tok0 * IND;

    // accumulators: 8 tokens x 4 column-pairs (cols j0 = 2*lane + 64*u)
    unsigned long long acc2[8][4];
    #pragma unroll
    for (int t = 0; t < 8; t++)
        #pragma unroll
        for (int u = 0; u < 4; u++) acc2[t][u] = 0ull;

    // ---- stage A: h1 = x @ W1  (x from gmem via shfl groups, ping-pong weights) ----
    float xcur[8], xnxt[8];
    #pragma unroll
    for (int t = 0; t < 8; t++) xcur[t] = __ldg(xg + (8 * w + t) * IND + lane);
    #pragma unroll
    for (int t = 0; t < 8; t++) xnxt[t] = __ldg(xg + (8 * w + t) * IND + 32 + lane);

    float4 pA, pB;
    {   // chunk 0 -> WB0, prefetch chunk 1
        const float4* wg = (const float4*)W1;
        pA = wg[tid]; pB = wg[tid + 256];
        ((float4*)WB0)[tid] = pA; ((float4*)WB0)[tid + 256] = pB;
        const float4* wg1 = (const float4*)(W1 + 8 * HH);
        pA = wg1[tid]; pB = wg1[tid + 256];
    }
    __syncthreads();

    #pragma unroll
    for (int cc = 0; cc < IND / 8; cc++) {               // 16 chunks
        float* cur = (cc & 1) ? WB1 : WB0;
        float* nxt = (cc & 1) ? WB0 : WB1;
        if (cc + 1 < IND / 8) {                           // store prefetched chunk cc+1
            ((float4*)nxt)[tid] = pA; ((float4*)nxt)[tid + 256] = pB;
        }
        if (cc + 2 < IND / 8) {                           // prefetch chunk cc+2
            const float4* wg = (const float4*)(W1 + (size_t)(cc + 2) * 8 * HH);
            pA = wg[tid]; pB = wg[tid + 256];
        }
        if ((cc & 3) == 0 && cc > 0) {                    // new 32-k group
            #pragma unroll
            for (int t = 0; t < 8; t++) xcur[t] = xnxt[t];
            int g32 = (cc >> 2) * 32 + 32;
            if (g32 < IND) {
                #pragma unroll
                for (int t = 0; t < 8; t++)
                    xnxt[t] = __ldg(xg + (8 * w + t) * IND + g32 + lane);
            }
        }
        #pragma unroll
        for (int k = 0; k < 8; k++) {
            const int kk = ((cc & 3) << 3) + k;
            unsigned long long xp[8];
            #pragma unroll
            for (int t = 0; t < 8; t++) {
                float xs = __shfl_sync(~0u, xcur[t], kk);
                xp[t] = pk2(xs, xs);
            }
            #pragma unroll
            for (int u = 0; u < 4; u++) {
                unsigned long long wv2 =
                    *(const unsigned long long*)&cur[k * HH + 2 * lane + 64 * u];
                #pragma unroll
                for (int t = 0; t < 8; t++) fma2(acc2[t][u], xp[t], wv2);
            }
        }
        __syncthreads();
    }
    #pragma unroll
    for (int u = 0; u < 4; u++) {
        int j0 = 2 * lane + 64 * u;
        float2 bb2 = *(const float2*)&b1[j0];
        #pragma unroll
        for (int t = 0; t < 8; t++) {
            float lo, hi;
            upk2(acc2[t][u], lo, hi);
            *(float2*)&SH1[(8 * w + t) * HH + j0] = make_float2(lo + bb2.x, hi + bb2.y);
        }
    }
    __syncthreads();

    // ---- LayerNorm stats (warp w: tokens 8w..8w+7) ----
    #pragma unroll
    for (int i = 0; i < 8; i++) {
        int t = 8 * w + i;
        float s = 0.f, ss = 0.f;
        #pragma unroll
        for (int u = 0; u < 8; u++) {
            float v = SH1[t * HH + lane + 32 * u];
            s += v; ss = fmaf(v, v, ss);
        }
        s = wsum(s); ss = wsum(ss);
        if (lane == 0) {
            float mu = s * (1.f / HH);
            float var = ss * (1.f / HH) - mu * mu;
            MUS[2 * t] = mu;
            MUS[2 * t + 1] = rsqrtf(var + 1e-5f);
        }
    }
    __syncthreads();

    // ---- LN transform + GELU in place ----
    {
        float gv = lng[tid], bv = lnb[tid];
        #pragma unroll 8
        for (int t = 0; t < TPB; t++) {
            float v = SH1[t * HH + tid];
            v = (v - MUS[2 * t]) * MUS[2 * t + 1] * gv + bv;
            SH1[t * HH + tid] = gelu_exact(v);
        }
    }
    __syncthreads();

    // ---- stage B: h2 = gelu(g1 @ W2 + b2) ----
    #pragma unroll
    for (int t = 0; t < 8; t++)
        #pragma unroll
        for (int u = 0; u < 4; u++) acc2[t][u] = 0ull;

    #pragma unroll
    for (int t = 0; t < 8; t++) xcur[t] = SH1[(8 * w + t) * HH + lane];
    #pragma unroll
    for (int t = 0; t < 8; t++) xnxt[t] = SH1[(8 * w + t) * HH + 32 + lane];

    {   // chunk 0 -> WB0, prefetch chunk 1
        const float4* wg = (const float4*)W2;
        pA = wg[tid]; pB = wg[tid + 256];
        ((float4*)WB0)[tid] = pA; ((float4*)WB0)[tid + 256] = pB;
        const float4* wg1 = (const float4*)(W2 + 8 * HH);
        pA = wg1[tid]; pB = wg1[tid + 256];
    }
    __syncthreads();

    #pragma unroll
    for (int cc = 0; cc < HH / 8; cc++) {                 // 32 chunks
        float* cur = (cc & 1) ? WB1 : WB0;
        float* nxt = (cc & 1) ? WB0 : WB1;
        if (cc + 1 < HH / 8) {
            ((float4*)nxt)[tid] = pA; ((float4*)nxt)[tid + 256] = pB;
        }
        if (cc + 2 < HH / 8) {
            const float4* wg = (const float4*)(W2 + (size_t)(cc + 2) * 8 * HH);
            pA = wg[tid]; pB = wg[tid + 256];
        }
        if ((cc & 3) == 0 && cc > 0) {
            #pragma unroll
            for (int t = 0; t < 8; t++) xcur[t] = xnxt[t];
            int g32 = (cc >> 2) * 32 + 32;
            if (g32 < HH) {
                #pragma unroll
                for (int t = 0; t < 8; t++)
                    xnxt[t] = SH1[(8 * w + t) * HH + g32 + lane];
            }
        }
        #pragma unroll
        for (int k = 0; k < 8; k++) {
            const int kk = ((cc & 3) << 3) + k;
            unsigned long long xp[8];
            #pragma unroll
            for (int t = 0; t < 8; t++) {
                float xs = __shfl_sync(~0u, xcur[t], kk);
                xp[t] = pk2(xs, xs);
            }
            #pragma unroll
            for (int u = 0; u < 4; u++) {
                unsigned long long wv2 =
                    *(const unsigned long long*)&cur[k * HH + 2 * lane + 64 * u];
                #pragma unroll
                for (int t = 0; t < 8; t++) fma2(acc2[t][u], xp[t], wv2);
            }
        }
        __syncthreads();
    }
    // all SH1 reads complete (loop ends with syncthreads) -> overlay with SH2
    #pragma unroll
    for (int u = 0; u < 4; u++) {
        int j0 = 2 * lane + 64 * u;
        float2 bb2 = *(const float2*)&b2[j0];
        #pragma unroll
        for (int t = 0; t < 8; t++) {
            float lo, hi;
            upk2(acc2[t][u], lo, hi);
            *(float2*)&SH2[(8 * w + t) * HH + j0] =
                make_float2(gelu_exact(lo + bb2.x), gelu_exact(hi + bb2.y));
        }
    }
    __syncthreads();   // WB0/WB1 dead -> W3B region valid

    // ---- stage C: logits = h2 @ W3 + b3 -> log_softmax ----
    {
        const float4* wg = (const float4*)W3;
        float4* d = (float4*)W3B;
        #pragma unroll
        for (int i = 0; i < 8; i++) d[tid + 256 * i] = wg[tid + 256 * i];
    }
    __syncthreads();

    // token pairs p: (8w+2p, 8w+2p+1); lane = output state
    unsigned long long acc3[4] = {0ull, 0ull, 0ull, 0ull};
    for (int k4 = 0; k4 < HH / 4; k4++) {
        float4 xa[8];
        #pragma unroll
        for (int t = 0; t < 8; t++)
            xa[t] = *(const float4*)&SH2[(8 * w + t) * HH + 4 * k4];   // broadcast
        #pragma unroll
        for (int q = 0; q < 4; q++) {
            float wv = W3B[(4 * k4 + q) * SS + lane];
            unsigned long long wv2 = pk2(wv, wv);
            #pragma unroll
            for (int p = 0; p < 4; p++) {
                float x0 = q == 0 ? xa[2 * p].x : q == 1 ? xa[2 * p].y : q == 2 ? xa[2 * p].z : xa[2 * p].w;
                float x1 = q == 0 ? xa[2 * p + 1].x : q == 1 ? xa[2 * p + 1].y : q == 2 ? xa[2 * p + 1].z : xa[2 * p + 1].w;
                fma2(acc3[p], pk2(x0, x1), wv2);
            }
        }
    }
    float bbv = b3[lane];
    #pragma unroll
    for (int p = 0; p < 4; p++) {
        float v0, v1;
        upk2(acc3[p], v0, v1);
        #pragma unroll
        for (int h = 0; h < 2; h++) {
            float v = (h == 0 ? v0 : v1) + bbv;
            float m = wmax(v);
            float e = expf(v - m);
            float s = wsum(e);
            emis[(tok0 + 8 * w + 2 * p + h) * SS + lane] = v - m - logf(s);
        }
    }

    // ---- publish chunk ----
    __threadfence();
    __syncthreads();
    if (tid == 0) atomicExch(&g_flag[imlp], 1);
}

// ---------------- backtrace: segment composition ----------------
__global__ void __launch_bounds__(1024) k_backtrace(float* __restrict__ bp_out)
{
    __shared__ int comp[32][32];
    __shared__ int entry_s[32];
    const int b = blockIdx.x;
    const int seg = threadIdx.x >> 5, e = threadIdx.x & 31;
    const unsigned char* bp = g_bp + (size_t)b * TT * SS;
    const int tTop = seg * 256 + 255;

    int st = e;
    for (int t = tTop; t >= seg * 256 + 1; t--)
        st = bp[(size_t)t * SS + st];
    comp[seg][e] = st;
    __syncthreads();

    if (threadIdx.x == 0) {
        int cur = g_last[b];
        for (int s = 31; s >= 0; s--) {
            entry_s[s] = cur;
            int ex = comp[s][cur];
            if (s > 0) cur = bp[(size_t)(256 * s) * SS + ex];
        }
    }
    __syncthreads();

    if (e == 0) {
        int cur = entry_s[seg];
        float* o = bp_out + (size_t)b * TT;
        o[tTop] = (float)cur;
        for (int t = tTop; t >= seg * 256 + 1; t--) {
            cur = bp[(size_t)t * SS + cur];
            o[t - 1] = (float)cur;
        }
    }
}

extern "C" void kernel_launch(void* const* d_in, const int* in_sizes, int n_in,
                              void* d_out, int out_size)
{
    const float* x   = (const float*)d_in[0];
    const float* il  = (const float*)d_in[1];
    const float* tl  = (const float*)d_in[2];
    const float* W1  = (const float*)d_in[3];
    const float* b1  = (const float*)d_in[4];
    const float* lng = (const float*)d_in[5];
    const float* lnb = (const float*)d_in[6];
    const float* W2  = (const float*)d_in[7];
    const float* b2  = (const float*)d_in[8];
    const float* W3  = (const float*)d_in[9];
    const float* b3  = (const float*)d_in[10];
    float* out = (float*)d_out;

    static bool attr_done = false;
    if (!attr_done) {
        cudaFuncSetAttribute(k_fused, cudaFuncAttributeMaxDynamicSharedMemorySize, MLP_SMEM_BYTES);
        attr_done = true;
    }

    k_params<<<1, 1024>>>(il, tl, out + TRANS_OFF);
    k_fused<<<NSCAN + NMLP, 256, MLP_SMEM_BYTES>>>(x, W1, b1, lng, lnb, W2, b2, W3, b3,
                                                   out, out + PROBS_OFF,
                                                   out + LL_OFF, out + PS_OFF);
    k_backtrace<<<BB, 1024>>>(out + BP_OFF);
}

// round 10
// speedup vs baseline: 1.1214x; 1.0098x over previous
#include <cuda_runtime.h>
#include <math.h>

#define BB   32
#define TT   8192
#define SS   32
#define IND  128
#define HH   256
#define NTOK (BB*TT)
#define TPB  64                 // tokens per MLP block
#define NMLP (NTOK/TPB)         // 4096
#define NCHUNK (TT/TPB)         // 128 chunks per batch
#define NSCAN 16                // scan blocks (2 batches each)

// output section offsets (floats): emissions, state_probs, ll, trans, best_path, path_score
#define PROBS_OFF  8388608L
#define LL_OFF     16777216L
#define TRANS_OFF  16777248L
#define BP_OFF     16778272L
#define PS_OFF     17040416L

__device__ unsigned char g_bp[(size_t)NTOK * SS];
__device__ float g_trans[SS * SS];
__device__ float g_logtrans[SS * SS];
__device__ float g_loginit[SS];
__device__ int   g_last[BB];
__device__ int   g_flag[BB * NCHUNK];

__device__ __forceinline__ float gelu_exact(float v) {
    return 0.5f * v * (1.0f + erff(v * 0.70710678118654752440f));
}
__device__ __forceinline__ float wmax(float v) {
    #pragma unroll
    for (int o = 16; o; o >>= 1) v = fmaxf(v, __shfl_xor_sync(~0u, v, o));
    return v;
}
__device__ __forceinline__ float wsum(float v) {
    #pragma unroll
    for (int o = 16; o; o >>= 1) v += __shfl_xor_sync(~0u, v, o);
    return v;
}
__device__ __forceinline__ unsigned long long pk2(float lo, float hi) {
    unsigned long long r;
    asm("mov.b64 %0, {%1, %2};" : "=l"(r) : "f"(lo), "f"(hi));
    return r;
}
__device__ __forceinline__ void fma2(unsigned long long& acc, unsigned long long a,
                                     unsigned long long b) {
    asm("fma.rn.f32x2 %0, %1, %2, %0;" : "+l"(acc) : "l"(a), "l"(b));
}
__device__ __forceinline__ void upk2(unsigned long long v, float& lo, float& hi) {
    asm("mov.b64 {%0, %1}, %2;" : "=f"(lo), "=f"(hi) : "l"(v));
}

// ---------------- kernel 0: params + flag reset ----------------
__global__ void __launch_bounds__(1024) k_params(const float* __restrict__ il,
                                                 const float* __restrict__ tl,
                                                 float* __restrict__ trans_out)
{
    const int w = threadIdx.x >> 5, lane = threadIdx.x & 31;
    for (int i = threadIdx.x; i < BB * NCHUNK; i += 1024) g_flag[i] = 0;
    {
        float vv = tl[w * SS + lane];
        float m = wmax(vv);
        float e = expf(vv - m);
        float s = wsum(e);
        float tr = e / s;
        g_trans[w * SS + lane] = tr;
        trans_out[w * SS + lane] = tr;
        g_logtrans[w * SS + lane] = logf(tr + 1e-10f);
    }
    if (w == 0) {
        float vv = il[lane];
        float m = wmax(vv);
        float e = expf(vv - m);
        float s = wsum(e);
        g_loginit[lane] = logf(e / s + 1e-10f);
    }
}

// ---------------- fused kernel ----------------
// smem floats (28672 = 114688 B = 14 x 8KB pages -> 2 blocks/SM):
//   SH1 @0      [64][256] (16384)  -- SH2 overlays after stage B (post-sync)
//   WB  @16384  [16][256] (4096)   -- weight k-chunk
//   SX  @20480  [64][128] (8192)   -- dead after stage A;
//                                     MUS overlays @20480 (post-stage-A),
//                                     W3B overlays @20480 in stage C (MUS dead)
#define SM_FLOATS 28672
#define MLP_SMEM_BYTES (SM_FLOATS * 4)

__global__ void __launch_bounds__(256, 2) k_fused(
    const float* __restrict__ x,
    const float* __restrict__ W1, const float* __restrict__ b1,
    const float* __restrict__ lng, const float* __restrict__ lnb,
    const float* __restrict__ W2, const float* __restrict__ b2,
    const float* __restrict__ W3, const float* __restrict__ b3,
    float* emis, float* probs, float* ll, float* ps)
{
    // ================= scan blocks (persistent consumers) =================
    if (blockIdx.x < NSCAN) {
        const int wid = threadIdx.x >> 5, j = threadIdx.x & 31;
        if (wid >= 4) return;
        const int b = 2 * (int)blockIdx.x + (wid >> 1);
        const float* em = emis + (size_t)b * TT * SS;

        if ((wid & 1) == 0) {
            // forward scan (lagged-max rescaled) + fused state_probs
            float* pr = probs + (size_t)b * TT * SS;
            float tr[32];
            #pragma unroll
            for (int i = 0; i < 32; i++) tr[i] = g_trans[i * SS + j] + 1e-10f;

            float a = 0.f, m = 0.f, mnext = 0.f;
            for (int c = 0; c < NCHUNK; c++) {
                while (__ldcg(&g_flag[c * BB + b]) == 0) __nanosleep(64);
                __threadfence();
                int t0 = TPB * c;
                const int t1 = t0 + TPB - 1;
                if (c == 0) {
                    a = g_loginit[j] + __ldcg(em + j);
                    m = wmax(a);
                    mnext = m;
                    float e0 = __expf(a - m);
                    float s0 = wsum(e0);
                    pr[j] = __fdividef(e0, s0);
                    t0 = 1;
                }
                float emA = __ldcg(em + (size_t)t0 * SS + j);
                float emB = __ldcg(em + (size_t)((t0 + 1 <= t1) ? t0 + 1 : t1) * SS + j);
                for (int t = t0; t <= t1; t++) {
                    float emv = emA; emA = emB;
                    int tn = (t + 2 <= t1) ? t + 2 : t1;
                    emB = __ldcg(em + (size_t)tn * SS + j);

                    float e = __expf(a - m);
                    float s0 = 0.f, s1 = 0.f, s2 = 0.f, s3 = 0.f;
                    #pragma unroll
                    for (int i = 0; i < 32; i += 4) {
                        s0 = fmaf(__shfl_sync(~0u, e, i    ), tr[i    ], s0);
                        s1 = fmaf(__shfl_sync(~0u, e, i + 1), tr[i + 1], s1);
                        s2 = fmaf(__shfl_sync(~0u, e, i + 2), tr[i + 2], s2);
                        s3 = fmaf(__shfl_sync(~0u, e, i + 3), tr[i + 3], s3);
                    }
                    a = emv + m + __logf((s0 + s1) + (s2 + s3));
                    m = mnext;
                    mnext = wmax(a);
                    float e2 = __expf(a - mnext);
                    float ss = wsum(e2);
                    pr[(size_t)t * SS + j] = __fdividef(e2, ss);
                }
            }
            float e = __expf(a - mnext);
            float sum = wsum(e);
            if (j == 0) ll[b] = mnext + __logf(sum);
        } else {
            // Viterbi scan
            unsigned char* bprow = g_bp + (size_t)b * TT * SS;
            float lt[32];
            #pragma unroll
            for (int i = 0; i < 32; i++) lt[i] = g_logtrans[i * SS + j];

            float v = 0.f;
            for (int c = 0; c < NCHUNK; c++) {
                while (__ldcg(&g_flag[c * BB + b]) == 0) __nanosleep(64);
                __threadfence();
                int t0 = TPB * c;
                const int t1 = t0 + TPB - 1;
                if (c == 0) {
                    v = g_loginit[j] + __ldcg(em + j);
                    t0 = 1;
                }
                float emA = __ldcg(em + (size_t)t0 * SS + j);
                float emB = __ldcg(em + (size_t)((t0 + 1 <= t1) ? t0 + 1 : t1) * SS + j);
                for (int t = t0; t <= t1; t++) {
                    float emv = emA; emA = emB;
                    int tn = (t + 2 <= t1) ? t + 2 : t1;
                    emB = __ldcg(em + (size_t)tn * SS + j);

                    float bv[4]; int bi[4];
                    #pragma unroll
                    for (int cc = 0; cc < 4; cc++) {
                        const int base = cc * 8;
                        float best = __shfl_sync(~0u, v, base) + lt[base];
                        int idx = base;
                        #pragma unroll
                        for (int q = 1; q < 8; q++) {
                            float cand = __shfl_sync(~0u, v, base + q) + lt[base + q];
                            if (cand > best) { best = cand; idx = base + q; }
                        }
                        bv[cc] = best; bi[cc] = idx;
                    }
                    float best = bv[0]; int idx = bi[0];
                    #pragma unroll
                    for (int cc = 1; cc < 4; cc++)
                        if (bv[cc] > best) { best = bv[cc]; idx = bi[cc]; }
                    v = best + emv;
                    bprow[(size_t)t * SS + j] = (unsigned char)idx;
                }
            }
            float bvv = v; int bj = j;
            #pragma unroll
            for (int o = 16; o; o >>= 1) {
                float ov = __shfl_xor_sync(~0u, bvv, o);
                int   oi = __shfl_xor_sync(~0u, bj, o);
                if (ov > bvv || (ov == bvv && oi < bj)) { bvv = ov; bj = oi; }
            }
            if (j == 0) { ps[b] = bvv; g_last[b] = bj; }
        }
        return;
    }

    // ================= MLP blocks (producer), 64 tokens, time-major =================
    extern __shared__ float sm[];
    float* SH1 = sm;              // SH2 overlays post-stage-B
    float* SH2 = sm;
    float* WB  = sm + 16384;      // 4096 floats (16 rows x 256)
    float* SX  = sm + 20480;      // 8192 floats
    float* MUS = sm + 20480;      // overlays SX (written post-stage-A)
    float* W3B = sm + 20480;      // overlays SX/MUS in stage C

    const int tid = threadIdx.x;
    const int w = tid >> 5, lane = tid & 31;
    const int imlp = blockIdx.x - NSCAN;       // 0..4095
    const int cchunk = imlp >> 5;              // 0..127
    const int bb = imlp & 31;
    const size_t tok0 = (size_t)bb * TT + (size_t)TPB * cchunk;

    {   // load x tile: 64 tokens x 128 = 8192 floats
        const float4* xg = (const float4*)(x + tok0 * IND);
        float4* d = (float4*)SX;
        #pragma unroll
        for (int i = 0; i < 8; i++) d[tid + 256 * i] = xg[tid + 256 * i];
    }

    // accumulators: 8 tokens x 4 column-pairs (cols j0 = 2*lane + 64*u)
    unsigned long long acc2[8][4];
    #pragma unroll
    for (int t = 0; t < 8; t++)
        #pragma unroll
        for (int u = 0; u < 4; u++) acc2[t][u] = 0ull;

    // ---- stage A: h1 = x @ W1 (16-row weight chunks, reg prefetch) ----
    float4 pf0, pf1, pf2, pf3;
    {
        const float4* wg = (const float4*)W1;
        pf0 = wg[tid]; pf1 = wg[tid + 256]; pf2 = wg[tid + 512]; pf3 = wg[tid + 768];
    }
    for (int kc = 0; kc < IND; kc += 16) {
        __syncthreads();
        {   // natural-layout weight chunk [16][256]
            float4* d = (float4*)WB;
            d[tid] = pf0; d[tid + 256] = pf1; d[tid + 512] = pf2; d[tid + 768] = pf3;
        }
        __syncthreads();
        if (kc + 16 < IND) {
            const float4* wg = (const float4*)(W1 + (size_t)(kc + 16) * HH);
            pf0 = wg[tid]; pf1 = wg[tid + 256]; pf2 = wg[tid + 512]; pf3 = wg[tid + 768];
        }
        #pragma unroll
        for (int k = 0; k < 16; k++) {
            unsigned long long xp[8];
            #pragma unroll
            for (int t = 0; t < 8; t++) {
                float xs = SX[(8 * w + t) * IND + kc + k];   // broadcast
                xp[t] = pk2(xs, xs);
            }
            #pragma unroll
            for (int u = 0; u < 4; u++) {
                unsigned long long wv2 =
                    *(const unsigned long long*)&WB[k * HH + 2 * lane + 64 * u];
                #pragma unroll
                for (int t = 0; t < 8; t++) fma2(acc2[t][u], xp[t], wv2);
            }
        }
    }
    __syncthreads();    // SX reads complete -> SX region free (MUS may be written)
    #pragma unroll
    for (int u = 0; u < 4; u++) {
        int j0 = 2 * lane + 64 * u;
        float2 bb2 = *(const float2*)&b1[j0];
        #pragma unroll
        for (int t = 0; t < 8; t++) {
            float lo, hi;
            upk2(acc2[t][u], lo, hi);
            *(float2*)&SH1[(8 * w + t) * HH + j0] = make_float2(lo + bb2.x, hi + bb2.y);
        }
    }
    __syncthreads();

    // ---- LayerNorm stats (warp w: tokens 8w..8w+7) ----
    #pragma unroll
    for (int i = 0; i < 8; i++) {
        int t = 8 * w + i;
        float s = 0.f, ss = 0.f;
        #pragma unroll
        for (int u = 0; u < 8; u++) {
            float v = SH1[t * HH + lane + 32 * u];
            s += v; ss = fmaf(v, v, ss);
        }
        s = wsum(s); ss = wsum(ss);
        if (lane == 0) {
            float mu = s * (1.f / HH);
            float var = ss * (1.f / HH) - mu * mu;
            MUS[2 * t] = mu;
            MUS[2 * t + 1] = rsqrtf(var + 1e-5f);
        }
    }
    __syncthreads();

    // ---- LN transform + GELU in place ----
    {
        float gv = lng[tid], bv = lnb[tid];
        #pragma unroll 8
        for (int t = 0; t < TPB; t++) {
            float v = SH1[t * HH + tid];
            v = (v - MUS[2 * t]) * MUS[2 * t + 1] * gv + bv;
            SH1[t * HH + tid] = gelu_exact(v);
        }
    }

    // ---- stage B: h2 = gelu(g1 @ W2 + b2) ----
    #pragma unroll
    for (int t = 0; t < 8; t++)
        #pragma unroll
        for (int u = 0; u < 4; u++) acc2[t][u] = 0ull;

    {
        const float4* wg = (const float4*)W2;
        pf0 = wg[tid]; pf1 = wg[tid + 256]; pf2 = wg[tid + 512]; pf3 = wg[tid + 768];
    }
    for (int kc = 0; kc < HH; kc += 16) {
        __syncthreads();
        {
            float4* d = (float4*)WB;
            d[tid] = pf0; d[tid + 256] = pf1; d[tid + 512] = pf2; d[tid + 768] = pf3;
        }
        __syncthreads();
        if (kc + 16 < HH) {
            const float4* wg = (const float4*)(W2 + (size_t)(kc + 16) * HH);
            pf0 = wg[tid]; pf1 = wg[tid + 256]; pf2 = wg[tid + 512]; pf3 = wg[tid + 768];
        }
        #pragma unroll
        for (int k = 0; k < 16; k++) {
            unsigned long long xp[8];
            #pragma unroll
            for (int t = 0; t < 8; t++) {
                float xs = SH1[(8 * w + t) * HH + kc + k];   // broadcast
                xp[t] = pk2(xs, xs);
            }
            #pragma unroll
            for (int u = 0; u < 4; u++) {
                unsigned long long wv2 =
                    *(const unsigned long long*)&WB[k * HH + 2 * lane + 64 * u];
                #pragma unroll
                for (int t = 0; t < 8; t++) fma2(acc2[t][u], xp[t], wv2);
            }
        }
    }
    __syncthreads();   // all SH1 reads complete -> safe to overlay with SH2
    #pragma unroll
    for (int u = 0; u < 4; u++) {
        int j0 = 2 * lane + 64 * u;
        float2 bb2 = *(const float2*)&b2[j0];
        #pragma unroll
        for (int t = 0; t < 8; t++) {
            float lo, hi;
            upk2(acc2[t][u], lo, hi);
            *(float2*)&SH2[(8 * w + t) * HH + j0] =
                make_float2(gelu_exact(lo + bb2.x), gelu_exact(hi + bb2.y));
        }
    }
    __syncthreads();   // WB/SX/MUS dead -> W3B region valid

    // ---- stage C: logits = h2 @ W3 + b3 -> log_softmax ----
    {
        const float4* wg = (const float4*)W3;
        float4* d = (float4*)W3B;
        #pragma unroll
        for (int i = 0; i < 8; i++) d[tid + 256 * i] = wg[tid + 256 * i];
    }
    __syncthreads();

    // token pairs p: (8w+2p, 8w+2p+1); lane = output state
    unsigned long long acc3[4] = {0ull, 0ull, 0ull, 0ull};
    for (int k4 = 0; k4 < HH / 4; k4++) {
        float4 xa[8];
        #pragma unroll
        for (int t = 0; t < 8; t++)
            xa[t] = *(const float4*)&SH2[(8 * w + t) * HH + 4 * k4];   // broadcast
        #pragma unroll
        for (int q = 0; q < 4; q++) {
            float wv = W3B[(4 * k4 + q) * SS + lane];
            unsigned long long wv2 = pk2(wv, wv);
            #pragma unroll
            for (int p = 0; p < 4; p++) {
                float x0 = q == 0 ? xa[2 * p].x : q == 1 ? xa[2 * p].y : q == 2 ? xa[2 * p].z : xa[2 * p].w;
                float x1 = q == 0 ? xa[2 * p + 1].x : q == 1 ? xa[2 * p + 1].y : q == 2 ? xa[2 * p + 1].z : xa[2 * p + 1].w;
                fma2(acc3[p], pk2(x0, x1), wv2);
            }
        }
    }
    float bbv = b3[lane];
    #pragma unroll
    for (int p = 0; p < 4; p++) {
        float v0, v1;
        upk2(acc3[p], v0, v1);
        #pragma unroll
        for (int h = 0; h < 2; h++) {
            float v = (h == 0 ? v0 : v1) + bbv;
            float m = wmax(v);
            float e = expf(v - m);
            float s = wsum(e);
            emis[(tok0 + 8 * w + 2 * p + h) * SS + lane] = v - m - logf(s);
        }
    }

    // ---- publish chunk ----
    __threadfence();
    __syncthreads();
    if (tid == 0) atomicExch(&g_flag[imlp], 1);
}

// ---------------- backtrace: segment composition ----------------
__global__ void __launch_bounds__(1024) k_backtrace(float* __restrict__ bp_out)
{
    __shared__ int comp[32][32];
    __shared__ int entry_s[32];
    const int b = blockIdx.x;
    const int seg = threadIdx.x >> 5, e = threadIdx.x & 31;
    const unsigned char* bp = g_bp + (size_t)b * TT * SS;
    const int tTop = seg * 256 + 255;

    int st = e;
    for (int t = tTop; t >= seg * 256 + 1; t--)
        st = bp[(size_t)t * SS + st];
    comp[seg][e] = st;
    __syncthreads();

    if (threadIdx.x == 0) {
        int cur = g_last[b];
        for (int s = 31; s >= 0; s--) {
            entry_s[s] = cur;
            int ex = comp[s][cur];
            if (s > 0) cur = bp[(size_t)(256 * s) * SS + ex];
        }
    }
    __syncthreads();

    if (e == 0) {
        int cur = entry_s[seg];
        float* o = bp_out + (size_t)b * TT;
        o[tTop] = (float)cur;
        for (int t = tTop; t >= seg * 256 + 1; t--) {
            cur = bp[(size_t)t * SS + cur];
            o[t - 1] = (float)cur;
        }
    }
}

extern "C" void kernel_launch(void* const* d_in, const int* in_sizes, int n_in,
                              void* d_out, int out_size)
{
    const float* x   = (const float*)d_in[0];
    const float* il  = (const float*)d_in[1];
    const float* tl  = (const float*)d_in[2];
    const float* W1  = (const float*)d_in[3];
    const float* b1  = (const float*)d_in[4];
    const float* lng = (const float*)d_in[5];
    const float* lnb = (const float*)d_in[6];
    const float* W2  = (const float*)d_in[7];
    const float* b2  = (const float*)d_in[8];
    const float* W3  = (const float*)d_in[9];
    const float* b3  = (const float*)d_in[10];
    float* out = (float*)d_out;

    static bool attr_done = false;
    if (!attr_done) {
        cudaFuncSetAttribute(k_fused, cudaFuncAttributeMaxDynamicSharedMemorySize, MLP_SMEM_BYTES);
        attr_done = true;
    }

    k_params<<<1, 1024>>>(il, tl, out + TRANS_OFF);
    k_fused<<<NSCAN + NMLP, 256, MLP_SMEM_BYTES>>>(x, W1, b1, lng, lnb, W2, b2, W3, b3,
                                                   out, out + PROBS_OFF,
                                                   out + LL_OFF, out + PS_OFF);
    k_backtrace<<<BB, 1024>>>(out + BP_OFF);
}